// round 15
// baseline (speedup 1.0000x reference)
#include <cuda_runtime.h>
#include <cstdint>

#define D 512
#define EPS 1e-9f
#define NCTAS 148                  // persistent: 1 CTA/SM (forced by smem)
#define SROWS 16                   // rows per stage -> 32KB per bulk op
#define NSTAGES 3
#define LROWS 4                    // direct-LDG side-stream rows per stage iter
#define ROW_BYTES (D * 4)          // 2048
#define STAGE_FLOATS (SROWS * D)   // 8192 floats = 32KB per array per stage
#define SMEM_BYTES (NSTAGES * 2 * STAGE_FLOATS * 4)   // 192 KB

// Accumulators: [0]=sum_e, [1]=sum_e2, [2]=sum_t, [3]=sum_t2, [4]=sum_et
// Zero at module load; last block re-zeroes after consuming, so the invariant
// "g_acc == 0, g_ticket == 0 at kernel entry" holds on every graph replay.
__device__ float g_acc[5 * D];
__device__ unsigned int g_ticket;

__device__ __forceinline__ unsigned s2u(const void* p) {
    return (unsigned)__cvta_generic_to_shared(p);
}

__device__ __forceinline__ void bulk_ld(unsigned sdst, const float* gsrc,
                                        unsigned bytes, unsigned mb) {
    asm volatile(
        "cp.async.bulk.shared::cluster.global.mbarrier::complete_tx::bytes "
        "[%0], [%1], %2, [%3];"
        :: "r"(sdst), "l"(gsrc), "r"(bytes), "r"(mb) : "memory");
}

__device__ __forceinline__ void mbar_wait(unsigned mb, unsigned phase) {
    asm volatile(
        "{\n\t.reg .pred P;\n"
        "W%=:\n\t"
        "mbarrier.try_wait.parity.acquire.cta.shared::cta.b64 P, [%0], %1, 0x989680;\n\t"
        "@P bra.uni DONE%=;\n\t"
        "bra.uni W%=;\n"
        "DONE%=:\n\t}"
        :: "r"(mb), "r"(phase) : "memory");
}

extern __shared__ float smem[];

__global__ void __launch_bounds__(512, 1) stats_finalize_kernel(
        const float* __restrict__ e,
        const float* __restrict__ t,
        int B_rows,
        float* __restrict__ out,
        float B) {
    const int tid = threadIdx.x;          // thread = column (0..511)
    __shared__ uint64_t mbar[NSTAGES];

    // Balanced contiguous row range for this block (442 or 443 rows).
    const long long r0 = ((long long)blockIdx.x * B_rows) / NCTAS;
    const long long r1 = ((long long)(blockIdx.x + 1) * B_rows) / NCTAS;
    const int nrows = (int)(r1 - r0);

    // Split: first tma_rows via TMA pipeline, last ldg_rows via direct LDG
    // side-stream (disjoint bytes, two independent request streams into DRAM).
    const int ldg_rows = nrows / 5;
    const int tma_rows = nrows - ldg_rows;
    const int nst = (tma_rows + SROWS - 1) / SROWS;
    const long long lbase = r0 + tma_rows;   // first LDG row

    if (tid == 0) {
        #pragma unroll
        for (int s = 0; s < NSTAGES; ++s)
            asm volatile("mbarrier.init.shared.b64 [%0], 1;"
                         :: "r"(s2u(&mbar[s])) : "memory");
        asm volatile("fence.proxy.async.shared::cta;" ::: "memory");
    }
    __syncthreads();

    // Producer (tid 0 only): issue stage s as two 32KB bulk copies.
    auto issue = [&](int s) {
        if (s >= nst) return;
        const int rows = min(SROWS, tma_rows - s * SROWS);
        const unsigned bytes = (unsigned)rows * ROW_BYTES;
        const int slot = s % NSTAGES;
        float* se_ = smem + slot * 2 * STAGE_FLOATS;
        float* st_ = se_ + STAGE_FLOATS;
        const unsigned mb = s2u(&mbar[slot]);
        asm volatile("mbarrier.arrive.expect_tx.shared.b64 _, [%0], %1;"
                     :: "r"(mb), "r"(2u * bytes) : "memory");
        const long long gr = (r0 + (long long)s * SROWS) * D;
        bulk_ld(s2u(se_), e + gr, bytes, mb);
        bulk_ld(s2u(st_), t + gr, bytes, mb);
    };

    // Prologue: NSTAGES-1 = 2 stages in flight (128 KB).
    if (tid == 0) {
        #pragma unroll
        for (int s = 0; s < NSTAGES - 1; ++s) issue(s);
    }

    float a0 = 0.f, a1 = 0.f, a2 = 0.f, a3 = 0.f, a4 = 0.f;

    for (int i = 0; i < nst; ++i) {
        const int slot = i % NSTAGES;
        const unsigned phase = (unsigned)((i / NSTAGES) & 1);
        mbar_wait(s2u(&mbar[slot]), phase);   // stage i landed
        __syncthreads();                       // all threads past stage i-1's reads

        // Slot (i-1)%NSTAGES is provably free now: refill it BEFORE consuming.
        if (tid == 0) issue(i + NSTAGES - 1);

        // --- direct-LDG side-stream: LROWS rows per stage iteration ---
        const long long lr = lbase + (long long)i * LROWS;
        #pragma unroll
        for (int r = 0; r < LROWS; ++r) {
            if (lr + r < r1) {
                float ev = e[(lr + r) * D + tid];
                float tv = t[(lr + r) * D + tid];
                a0 += ev;  a1 += ev * ev;
                a2 += tv;  a3 += tv * tv;
                a4 += ev * tv;
            }
        }

        // --- TMA stage consume ---
        const float* se_ = smem + slot * 2 * STAGE_FLOATS;
        const float* st_ = se_ + STAGE_FLOATS;
        const int rmax = tma_rows - i * SROWS;

        if (rmax >= SROWS) {
            #pragma unroll
            for (int r = 0; r < SROWS; ++r) {
                float ev = se_[r * D + tid];
                float tv = st_[r * D + tid];
                a0 += ev;  a1 += ev * ev;
                a2 += tv;  a3 += tv * tv;
                a4 += ev * tv;
            }
        } else {
            for (int r = 0; r < rmax; ++r) {
                float ev = se_[r * D + tid];
                float tv = st_[r * D + tid];
                a0 += ev;  a1 += ev * ev;
                a2 += tv;  a3 += tv * tv;
                a4 += ev * tv;
            }
        }
    }

    // Leftover LDG rows not covered by the nst iterations (if any).
    for (long long lr = lbase + (long long)nst * LROWS; lr < r1; ++lr) {
        float ev = e[lr * D + tid];
        float tv = t[lr * D + tid];
        a0 += ev;  a1 += ev * ev;
        a2 += tv;  a3 += tv * tv;
        a4 += ev * tv;
    }

    atomicAdd(&g_acc[0 * D + tid], a0);
    atomicAdd(&g_acc[1 * D + tid], a1);
    atomicAdd(&g_acc[2 * D + tid], a2);
    atomicAdd(&g_acc[3 * D + tid], a3);
    atomicAdd(&g_acc[4 * D + tid], a4);

    // ---- last-block-done finalize ----
    __threadfence();
    __syncthreads();

    __shared__ bool is_last;
    if (tid == 0) {
        unsigned int t_ = atomicAdd(&g_ticket, 1u);
        is_last = (t_ == (unsigned int)(gridDim.x - 1));
    }
    __syncthreads();
    if (!is_last) return;

    float fse  = __ldcg(&g_acc[0 * D + tid]);
    float fse2 = __ldcg(&g_acc[1 * D + tid]);
    float fst  = __ldcg(&g_acc[2 * D + tid]);
    float fst2 = __ldcg(&g_acc[3 * D + tid]);
    float fset = __ldcg(&g_acc[4 * D + tid]);

    // Re-zero for the next graph replay.
    g_acc[0 * D + tid] = 0.f;
    g_acc[1 * D + tid] = 0.f;
    g_acc[2 * D + tid] = 0.f;
    g_acc[3 * D + tid] = 0.f;
    g_acc[4 * D + tid] = 0.f;
    if (tid == 0) g_ticket = 0u;

    float me = fse / B;
    float mt = fst / B;
    float var_e = (fse2 - B * me * me) / (B - 1.0f);   // ddof=1
    float var_t = (fst2 - B * mt * mt) / (B - 1.0f);
    float sd_e = sqrtf(fmaxf(var_e, 0.0f)) + EPS;
    float sd_t = sqrtf(fmaxf(var_t, 0.0f)) + EPS;

    float cov = fset - B * me * mt;
    float c = cov / (sd_e * sd_t) / B;
    float d = 1.0f - c;
    float partial = d * d;

    __shared__ float red[16];
    #pragma unroll
    for (int o = 16; o > 0; o >>= 1)
        partial += __shfl_down_sync(0xffffffffu, partial, o);
    if ((tid & 31) == 0) red[tid >> 5] = partial;
    __syncthreads();
    if (tid < 32) {
        float v = (tid < 16) ? red[tid] : 0.f;
        #pragma unroll
        for (int o = 8; o > 0; o >>= 1)
            v += __shfl_down_sync(0xffffffffu, v, o);
        if (tid == 0) out[0] = v;
    }
}

extern "C" void kernel_launch(void* const* d_in, const int* in_sizes, int n_in,
                              void* d_out, int out_size) {
    const float* e = (const float*)d_in[0];
    const float* t = (const float*)d_in[1];
    float* out = (float*)d_out;

    const long long total = in_sizes[0];
    const int B = (int)(total / D);          // 65536

    cudaFuncSetAttribute(stats_finalize_kernel,
                         cudaFuncAttributeMaxDynamicSharedMemorySize, SMEM_BYTES);
    stats_finalize_kernel<<<NCTAS, 512, SMEM_BYTES>>>(e, t, B, out, (float)B);
}

// round 16
// speedup vs baseline: 1.0487x; 1.0487x over previous
#include <cuda_runtime.h>
#include <cstdint>

#define D 512
#define EPS 1e-9f
#define NCTAS 148                  // persistent: 1 CTA/SM (forced by smem)
#define SROWS 16                   // rows per stage -> 32KB per bulk op
#define NSTAGES 3
#define ROW_BYTES (D * 4)          // 2048
#define STAGE_FLOATS (SROWS * D)   // 8192 floats = 32KB per array per stage
#define SMEM_BYTES (NSTAGES * 2 * STAGE_FLOATS * 4)   // 192 KB

// Accumulators: [0]=sum_e, [1]=sum_e2, [2]=sum_t, [3]=sum_t2, [4]=sum_et
// Zero at module load; last block re-zeroes after consuming, so the invariant
// "g_acc == 0, g_ticket == 0 at kernel entry" holds on every graph replay.
__device__ float g_acc[5 * D];
__device__ unsigned int g_ticket;

__device__ __forceinline__ unsigned s2u(const void* p) {
    return (unsigned)__cvta_generic_to_shared(p);
}

__device__ __forceinline__ void bulk_ld(unsigned sdst, const float* gsrc,
                                        unsigned bytes, unsigned mb) {
    asm volatile(
        "cp.async.bulk.shared::cluster.global.mbarrier::complete_tx::bytes "
        "[%0], [%1], %2, [%3];"
        :: "r"(sdst), "l"(gsrc), "r"(bytes), "r"(mb) : "memory");
}

__device__ __forceinline__ void mbar_wait(unsigned mb, unsigned phase) {
    asm volatile(
        "{\n\t.reg .pred P;\n"
        "W%=:\n\t"
        "mbarrier.try_wait.parity.acquire.cta.shared::cta.b64 P, [%0], %1, 0x989680;\n\t"
        "@P bra.uni DONE%=;\n\t"
        "bra.uni W%=;\n"
        "DONE%=:\n\t}"
        :: "r"(mb), "r"(phase) : "memory");
}

extern __shared__ float smem[];

__global__ void __launch_bounds__(512, 1) stats_finalize_kernel(
        const float* __restrict__ e,
        const float* __restrict__ t,
        int B_rows,
        float* __restrict__ out,
        float B) {
    const int tid = threadIdx.x;          // thread = column (0..511)
    __shared__ uint64_t mbar[NSTAGES];

    // Balanced contiguous row range for this block (442 or 443 rows).
    const long long r0 = ((long long)blockIdx.x * B_rows) / NCTAS;
    const long long r1 = ((long long)(blockIdx.x + 1) * B_rows) / NCTAS;
    const int nrows = (int)(r1 - r0);
    const int nst = (nrows + SROWS - 1) / SROWS;

    if (tid == 0) {
        #pragma unroll
        for (int s = 0; s < NSTAGES; ++s)
            asm volatile("mbarrier.init.shared.b64 [%0], 2;"   // 2 producer arrivals
                         :: "r"(s2u(&mbar[s])) : "memory");
        asm volatile("fence.proxy.async.shared::cta;" ::: "memory");
    }
    __syncthreads();

    // Dual producers: tid 0 issues the e copy, tid 256 issues the t copy.
    // Each does its own arrive.expect_tx (mbarrier count = 2 arrivals).
    const bool is_p0 = (tid == 0);
    const bool is_p1 = (tid == 256);

    auto issue = [&](int s) {
        if (s >= nst) return;
        const int rows = min(SROWS, nrows - s * SROWS);
        const unsigned bytes = (unsigned)rows * ROW_BYTES;
        const int slot = s % NSTAGES;
        float* se_ = smem + slot * 2 * STAGE_FLOATS;
        float* st_ = se_ + STAGE_FLOATS;
        const unsigned mb = s2u(&mbar[slot]);
        const long long gr = (r0 + (long long)s * SROWS) * D;
        asm volatile("mbarrier.arrive.expect_tx.shared.b64 _, [%0], %1;"
                     :: "r"(mb), "r"(bytes) : "memory");
        if (is_p0) bulk_ld(s2u(se_), e + gr, bytes, mb);
        else       bulk_ld(s2u(st_), t + gr, bytes, mb);
    };

    // Prologue: NSTAGES-1 = 2 stages in flight (128 KB).
    if (is_p0 || is_p1) {
        #pragma unroll
        for (int s = 0; s < NSTAGES - 1; ++s) issue(s);
    }

    float a0 = 0.f, a1 = 0.f, a2 = 0.f, a3 = 0.f, a4 = 0.f;

    for (int i = 0; i < nst; ++i) {
        const int slot = i % NSTAGES;
        const unsigned phase = (unsigned)((i / NSTAGES) & 1);
        mbar_wait(s2u(&mbar[slot]), phase);   // stage i landed
        __syncthreads();                       // all threads past stage i-1's reads

        // Slot (i-1)%NSTAGES is provably free now: refill it BEFORE consuming.
        if (is_p0 || is_p1) issue(i + NSTAGES - 1);

        const float* se_ = smem + slot * 2 * STAGE_FLOATS;
        const float* st_ = se_ + STAGE_FLOATS;
        const int rmax = nrows - i * SROWS;

        if (rmax >= SROWS) {
            #pragma unroll
            for (int r = 0; r < SROWS; ++r) {
                float ev = se_[r * D + tid];
                float tv = st_[r * D + tid];
                a0 += ev;  a1 += ev * ev;
                a2 += tv;  a3 += tv * tv;
                a4 += ev * tv;
            }
        } else {
            for (int r = 0; r < rmax; ++r) {
                float ev = se_[r * D + tid];
                float tv = st_[r * D + tid];
                a0 += ev;  a1 += ev * ev;
                a2 += tv;  a3 += tv * tv;
                a4 += ev * tv;
            }
        }
    }

    atomicAdd(&g_acc[0 * D + tid], a0);
    atomicAdd(&g_acc[1 * D + tid], a1);
    atomicAdd(&g_acc[2 * D + tid], a2);
    atomicAdd(&g_acc[3 * D + tid], a3);
    atomicAdd(&g_acc[4 * D + tid], a4);

    // ---- last-block-done finalize ----
    __threadfence();
    __syncthreads();

    __shared__ bool is_last;
    if (tid == 0) {
        unsigned int t_ = atomicAdd(&g_ticket, 1u);
        is_last = (t_ == (unsigned int)(gridDim.x - 1));
    }
    __syncthreads();
    if (!is_last) return;

    float fse  = __ldcg(&g_acc[0 * D + tid]);
    float fse2 = __ldcg(&g_acc[1 * D + tid]);
    float fst  = __ldcg(&g_acc[2 * D + tid]);
    float fst2 = __ldcg(&g_acc[3 * D + tid]);
    float fset = __ldcg(&g_acc[4 * D + tid]);

    // Re-zero for the next graph replay.
    g_acc[0 * D + tid] = 0.f;
    g_acc[1 * D + tid] = 0.f;
    g_acc[2 * D + tid] = 0.f;
    g_acc[3 * D + tid] = 0.f;
    g_acc[4 * D + tid] = 0.f;
    if (tid == 0) g_ticket = 0u;

    float me = fse / B;
    float mt = fst / B;
    float var_e = (fse2 - B * me * me) / (B - 1.0f);   // ddof=1
    float var_t = (fst2 - B * mt * mt) / (B - 1.0f);
    float sd_e = sqrtf(fmaxf(var_e, 0.0f)) + EPS;
    float sd_t = sqrtf(fmaxf(var_t, 0.0f)) + EPS;

    float cov = fset - B * me * mt;
    float c = cov / (sd_e * sd_t) / B;
    float d = 1.0f - c;
    float partial = d * d;

    __shared__ float red[16];
    #pragma unroll
    for (int o = 16; o > 0; o >>= 1)
        partial += __shfl_down_sync(0xffffffffu, partial, o);
    if ((tid & 31) == 0) red[tid >> 5] = partial;
    __syncthreads();
    if (tid < 32) {
        float v = (tid < 16) ? red[tid] : 0.f;
        #pragma unroll
        for (int o = 8; o > 0; o >>= 1)
            v += __shfl_down_sync(0xffffffffu, v, o);
        if (tid == 0) out[0] = v;
    }
}

extern "C" void kernel_launch(void* const* d_in, const int* in_sizes, int n_in,
                              void* d_out, int out_size) {
    const float* e = (const float*)d_in[0];
    const float* t = (const float*)d_in[1];
    float* out = (float*)d_out;

    const long long total = in_sizes[0];
    const int B = (int)(total / D);          // 65536

    cudaFuncSetAttribute(stats_finalize_kernel,
                         cudaFuncAttributeMaxDynamicSharedMemorySize, SMEM_BYTES);
    stats_finalize_kernel<<<NCTAS, 512, SMEM_BYTES>>>(e, t, B, out, (float)B);
}

// round 17
// speedup vs baseline: 1.0554x; 1.0064x over previous
#include <cuda_runtime.h>
#include <cstdint>

#define D 512
#define EPS 1e-9f
#define NCTAS 148                  // persistent: 1 CTA/SM (forced by smem)
#define SROWS 16                   // rows per stage -> 32KB per bulk op (optimal)
#define NSTAGES 3
#define ROW_BYTES (D * 4)          // 2048
#define STAGE_FLOATS (SROWS * D)   // 8192 floats = 32KB per array per stage
#define SMEM_BYTES (NSTAGES * 2 * STAGE_FLOATS * 4)   // 192 KB

// Accumulators: [0]=sum_e, [1]=sum_e2, [2]=sum_t, [3]=sum_t2, [4]=sum_et
// Zero at module load; last block re-zeroes after consuming, so the invariant
// "g_acc == 0, g_ticket == 0 at kernel entry" holds on every graph replay.
__device__ float g_acc[5 * D];
__device__ unsigned int g_ticket;

__device__ __forceinline__ unsigned s2u(const void* p) {
    return (unsigned)__cvta_generic_to_shared(p);
}

__device__ __forceinline__ void bulk_ld(unsigned sdst, const float* gsrc,
                                        unsigned bytes, unsigned mb) {
    asm volatile(
        "cp.async.bulk.shared::cluster.global.mbarrier::complete_tx::bytes "
        "[%0], [%1], %2, [%3];"
        :: "r"(sdst), "l"(gsrc), "r"(bytes), "r"(mb) : "memory");
}

__device__ __forceinline__ void mbar_wait(unsigned mb, unsigned phase) {
    asm volatile(
        "{\n\t.reg .pred P;\n"
        "W%=:\n\t"
        "mbarrier.try_wait.parity.acquire.cta.shared::cta.b64 P, [%0], %1, 0x989680;\n\t"
        "@P bra.uni DONE%=;\n\t"
        "bra.uni W%=;\n"
        "DONE%=:\n\t}"
        :: "r"(mb), "r"(phase) : "memory");
}

extern __shared__ float smem[];

__global__ void __launch_bounds__(512, 1) stats_finalize_kernel(
        const float* __restrict__ e,
        const float* __restrict__ t,
        int B_rows,
        float* __restrict__ out,
        float B) {
    const int tid = threadIdx.x;          // thread = column (0..511)
    __shared__ uint64_t mbar[NSTAGES];

    // Balanced contiguous row range for this block (442 or 443 rows).
    const long long r0 = ((long long)blockIdx.x * B_rows) / NCTAS;
    const long long r1 = ((long long)(blockIdx.x + 1) * B_rows) / NCTAS;
    const int nrows = (int)(r1 - r0);
    const int nst = (nrows + SROWS - 1) / SROWS;

    if (tid == 0) {
        #pragma unroll
        for (int s = 0; s < NSTAGES; ++s)
            asm volatile("mbarrier.init.shared.b64 [%0], 1;"
                         :: "r"(s2u(&mbar[s])) : "memory");
        asm volatile("fence.proxy.async.shared::cta;" ::: "memory");
    }
    __syncthreads();

    // Producer (tid 0 only): issue stage s as two 32KB bulk copies.
    auto issue = [&](int s) {
        if (s >= nst) return;
        const int rows = min(SROWS, nrows - s * SROWS);
        const unsigned bytes = (unsigned)rows * ROW_BYTES;
        const int slot = s % NSTAGES;
        float* se_ = smem + slot * 2 * STAGE_FLOATS;
        float* st_ = se_ + STAGE_FLOATS;
        const unsigned mb = s2u(&mbar[slot]);
        asm volatile("mbarrier.arrive.expect_tx.shared.b64 _, [%0], %1;"
                     :: "r"(mb), "r"(2u * bytes) : "memory");
        const long long gr = (r0 + (long long)s * SROWS) * D;
        bulk_ld(s2u(se_), e + gr, bytes, mb);
        bulk_ld(s2u(st_), t + gr, bytes, mb);
    };

    // Prologue: NSTAGES-1 = 2 stages in flight (128 KB).
    if (tid == 0) {
        #pragma unroll
        for (int s = 0; s < NSTAGES - 1; ++s) issue(s);
    }

    float a0 = 0.f, a1 = 0.f, a2 = 0.f, a3 = 0.f, a4 = 0.f;

    for (int i = 0; i < nst; ++i) {
        const int slot = i % NSTAGES;
        const unsigned phase = (unsigned)((i / NSTAGES) & 1);
        mbar_wait(s2u(&mbar[slot]), phase);   // stage i landed
        __syncthreads();                       // all threads past stage i-1's reads

        // Slot (i-1)%NSTAGES is provably free now: refill it BEFORE consuming.
        if (tid == 0) issue(i + NSTAGES - 1);

        const float* se_ = smem + slot * 2 * STAGE_FLOATS;
        const float* st_ = se_ + STAGE_FLOATS;
        const int rmax = nrows - i * SROWS;

        if (rmax >= SROWS) {
            #pragma unroll
            for (int r = 0; r < SROWS; ++r) {
                float ev = se_[r * D + tid];
                float tv = st_[r * D + tid];
                a0 += ev;  a1 += ev * ev;
                a2 += tv;  a3 += tv * tv;
                a4 += ev * tv;
            }
        } else {
            for (int r = 0; r < rmax; ++r) {
                float ev = se_[r * D + tid];
                float tv = st_[r * D + tid];
                a0 += ev;  a1 += ev * ev;
                a2 += tv;  a3 += tv * tv;
                a4 += ev * tv;
            }
        }
    }

    atomicAdd(&g_acc[0 * D + tid], a0);
    atomicAdd(&g_acc[1 * D + tid], a1);
    atomicAdd(&g_acc[2 * D + tid], a2);
    atomicAdd(&g_acc[3 * D + tid], a3);
    atomicAdd(&g_acc[4 * D + tid], a4);

    // ---- last-block-done finalize ----
    __threadfence();
    __syncthreads();

    __shared__ bool is_last;
    if (tid == 0) {
        unsigned int t_ = atomicAdd(&g_ticket, 1u);
        is_last = (t_ == (unsigned int)(gridDim.x - 1));
    }
    __syncthreads();
    if (!is_last) return;

    float fse  = __ldcg(&g_acc[0 * D + tid]);
    float fse2 = __ldcg(&g_acc[1 * D + tid]);
    float fst  = __ldcg(&g_acc[2 * D + tid]);
    float fst2 = __ldcg(&g_acc[3 * D + tid]);
    float fset = __ldcg(&g_acc[4 * D + tid]);

    // Re-zero for the next graph replay.
    g_acc[0 * D + tid] = 0.f;
    g_acc[1 * D + tid] = 0.f;
    g_acc[2 * D + tid] = 0.f;
    g_acc[3 * D + tid] = 0.f;
    g_acc[4 * D + tid] = 0.f;
    if (tid == 0) g_ticket = 0u;

    float me = fse / B;
    float mt = fst / B;
    float var_e = (fse2 - B * me * me) / (B - 1.0f);   // ddof=1
    float var_t = (fst2 - B * mt * mt) / (B - 1.0f);
    float sd_e = sqrtf(fmaxf(var_e, 0.0f)) + EPS;
    float sd_t = sqrtf(fmaxf(var_t, 0.0f)) + EPS;

    float cov = fset - B * me * mt;
    float c = cov / (sd_e * sd_t) / B;
    float d = 1.0f - c;
    float partial = d * d;

    __shared__ float red[16];
    #pragma unroll
    for (int o = 16; o > 0; o >>= 1)
        partial += __shfl_down_sync(0xffffffffu, partial, o);
    if ((tid & 31) == 0) red[tid >> 5] = partial;
    __syncthreads();
    if (tid < 32) {
        float v = (tid < 16) ? red[tid] : 0.f;
        #pragma unroll
        for (int o = 8; o > 0; o >>= 1)
            v += __shfl_down_sync(0xffffffffu, v, o);
        if (tid == 0) out[0] = v;
    }
}

extern "C" void kernel_launch(void* const* d_in, const int* in_sizes, int n_in,
                              void* d_out, int out_size) {
    const float* e = (const float*)d_in[0];
    const float* t = (const float*)d_in[1];
    float* out = (float*)d_out;

    const long long total = in_sizes[0];
    const int B = (int)(total / D);          // 65536

    cudaFuncSetAttribute(stats_finalize_kernel,
                         cudaFuncAttributeMaxDynamicSharedMemorySize, SMEM_BYTES);
    stats_finalize_kernel<<<NCTAS, 512, SMEM_BYTES>>>(e, t, B, out, (float)B);
}